// round 13
// baseline (speedup 1.0000x reference)
#include <cuda_runtime.h>

// InterConv: B=2048, F=39, E=64, C=64, P=741
// out[b, c*P + p] = relu( U[c][ii[p]] + V[c][jj[p]] ),  U = x@Wi^T + bias, V = x@Wj^T
//
// smem (floats), 48.7 KB -> 4 CTAs/SM:
//   phase 0/1: xs [0,2720) rows stride 17 f4;  Wi [2720,7072)  Wj [7072,11424)
//              (rows stride 17 f4);  tab [11424,12168) built in phase 0
//   phase 2 overlay: Uc [0,2624)  Vc [2624,5248)
//
// Phase 1 map: thread owns c in {cs, cs+32} and f = fg*5+k (k<5);
//   cs = (w&3)*8 + (lane&7), fg = (w>>2)*4 + (lane>>3).
//   Per e4: 4 W-LDS.128 (8 rows x 4-bcast, bank-disjoint -> 1 wf) +
//           5 xs-LDS.128 (4 rows x 8-bcast, bank-disjoint -> 1 wf) = 9 instr/9 wf.
//
// Phase 2: row-pairing (p0(c)=27c mod 32 == p0(c+32)); 22-entry tab window cached
// in registers per pair; both rows fused per iteration (2x ILP).

#define FN 39
#define EN 64
#define CN 64
#define PN 741            // 39*38/2
#define OUTB (CN * PN)    // 47424 floats per batch
#define THREADS 256

#define XS_OFF  0                       // 40 rows x 17 f4 = 2720 floats
#define WI_OFF  2720                    // 64 rows x 17 f4 = 4352 floats
#define WJ_OFF  7072
#define TAB_OFF 11424                   // 744 floats
#define UC_OFF  0                       // overlay
#define VC_OFF  2624
#define SMEM_FLOATS 12168
#define SMEM_BYTES  (SMEM_FLOATS * 4)   // 48672

// packed fp32x2 FMA (Blackwell; exact fp32 semantics, 2x FFMA throughput)
#define FMA_F32X2(acc, a, b) \
    asm("fma.rn.f32x2 %0, %1, %2, %0;" : "+l"(acc) : "l"(a), "l"(b))

extern __shared__ float smem[];

__global__ void __launch_bounds__(THREADS, 4)
interconv_kernel(const float* __restrict__ x,
                 const float* __restrict__ W,
                 const float* __restrict__ bias,
                 float* __restrict__ out)
{
    const int tid = threadIdx.x;
    const long long b = blockIdx.x;
    unsigned* tab = (unsigned*)(smem + TAB_OFF);

    // ---- Phase 0: stage x (stride 17) and W (stride 17); build tab -------
    {
        float4* xs4 = (float4*)(smem + XS_OFF);
        const float4* xb4 = (const float4*)(x + b * (long long)(FN * EN));
        #pragma unroll
        for (int it = 0; it < 3; it++) {
            int idx = tid + it * THREADS;
            if (idx < (FN * EN) / 4)
                xs4[idx + (idx >> 4)] = xb4[idx];   // slot f*17 + e4
        }
        if (tid < EN) {                             // zero pad row f=39 (e4<16)
            int e4 = tid >> 2, r = tid & 3;
            smem[XS_OFF + (39 * 17 + e4) * 4 + r] = 0.f;
        }

        // W gmem: [c][128] floats (k=0 -> Wi, k=1 -> Wj); smem stride 17 f4
        float4* Wi4 = (float4*)(smem + WI_OFF);
        float4* Wj4 = (float4*)(smem + WJ_OFF);
        const float4* Wg4 = (const float4*)W;
        #pragma unroll
        for (int it = 0; it < 8; it++) {
            int idx = tid + it * THREADS;           // 2048 float4 total
            int c = idx >> 5, q = idx & 31;
            float4 w = Wg4[idx];
            if (q < 16) Wi4[c * 17 + q] = w;
            else        Wj4[c * 17 + (q - 16)] = w;
        }

        // pair table (np.triu_indices(F,1) row-major): byte offsets i*4 | j*4<<16.
        // Built here so the ALU hides behind the outstanding LDGs above.
        for (int p = tid; p < PN; p += THREADS) {
            int i = 0, rem = p;
            while (rem >= FN - 1 - i) { rem -= FN - 1 - i; i++; }
            int j = i + 1 + rem;
            tab[p] = (unsigned)(i * 4) | ((unsigned)(j * 4) << 16);
        }
    }
    __syncthreads();

    // ---- Phase 1: U = x @ Wi^T + b, V = x @ Wj^T  (f32x2, 2c x 5f tile) --
    const int lane = tid & 31;
    const int wrp  = tid >> 5;
    const int cs = (wrp & 3) * 8 + (lane & 7);      // c-slot: owns cs and cs+32
    const int fg = (wrp >> 2) * 4 + (lane >> 3);    // f = fg*5 + k, k<5

    unsigned long long aua[5], aub[5], ava[5], avb[5];
    #pragma unroll
    for (int k = 0; k < 5; k++) { aua[k]=0ull; aub[k]=0ull; ava[k]=0ull; avb[k]=0ull; }

    {
        const ulonglong2* xsb = (const ulonglong2*)(smem + XS_OFF) + fg * 5 * 17;
        const ulonglong2* wia = (const ulonglong2*)(smem + WI_OFF) + cs * 17;
        const ulonglong2* wja = (const ulonglong2*)(smem + WJ_OFF) + cs * 17;

        #pragma unroll
        for (int e4 = 0; e4 < 16; e4++) {
            ulonglong2 wiA = wia[e4];
            ulonglong2 wiB = wia[32 * 17 + e4];
            ulonglong2 wjA = wja[e4];
            ulonglong2 wjB = wja[32 * 17 + e4];
            #pragma unroll
            for (int k = 0; k < 5; k++) {
                ulonglong2 xv = xsb[k * 17 + e4];   // f=39 row is zeros
                FMA_F32X2(aua[k], xv.x, wiA.x);
                FMA_F32X2(aua[k], xv.y, wiA.y);
                FMA_F32X2(aub[k], xv.x, wiB.x);
                FMA_F32X2(aub[k], xv.y, wiB.y);
                FMA_F32X2(ava[k], xv.x, wjA.x);
                FMA_F32X2(ava[k], xv.y, wjA.y);
                FMA_F32X2(avb[k], xv.x, wjB.x);
                FMA_F32X2(avb[k], xv.y, wjB.y);
            }
        }
    }
    __syncthreads();   // all xs/W reads done; safe to overlay

    // ---- Phase 1b: write Uc/Vc (transposed, stride 41) ------------------
    float* Uc = smem + UC_OFF;                 // [c][41]
    float* Vc = smem + VC_OFF;                 // [c][41]

    {
        const float bca = __ldg(bias + cs);
        const float bcb = __ldg(bias + cs + 32);
        #pragma unroll
        for (int k = 0; k < 5; k++) {
            int f = fg * 5 + k;                // f<=39; f=39 row never read
            float ua = __uint_as_float((unsigned)aua[k])
                     + __uint_as_float((unsigned)(aua[k] >> 32));
            float ub = __uint_as_float((unsigned)aub[k])
                     + __uint_as_float((unsigned)(aub[k] >> 32));
            float va = __uint_as_float((unsigned)ava[k])
                     + __uint_as_float((unsigned)(ava[k] >> 32));
            float vb = __uint_as_float((unsigned)avb[k])
                     + __uint_as_float((unsigned)(avb[k] >> 32));
            Uc[cs * 41 + f]        = ua + bca;   // bias folded into U
            Uc[(cs + 32) * 41 + f] = ub + bcb;
            Vc[cs * 41 + f]        = va;
            Vc[(cs + 32) * 41 + f] = vb;
        }
    }
    __syncthreads();

    // ---- Phase 2: expansion + relu, fused row pairs, register tab --------
    float* outb = out + b * (long long)OUTB;

    #pragma unroll 1
    for (int k = 0; k < 4; k++) {
        const int r  = wrp * 4 + k;           // rows r and r+32 share p0
        const int p0 = (27 * r) & 31;

        // preload the 22-entry aligned tab window into registers
        unsigned tw[22];
        {
            const unsigned* tb = tab + p0 + lane;
            #pragma unroll
            for (int it = 0; it < 22; it++) tw[it] = tb[it * 32];
        }

        const char* bu0 = (const char*)(Uc + r * 41);
        const char* bv0 = (const char*)(Vc + r * 41);
        const char* bu1 = (const char*)(Uc + (r + 32) * 41);
        const char* bv1 = (const char*)(Vc + (r + 32) * 41);
        float* po0 = outb + r * PN;
        float* po1 = outb + (r + 32) * PN;

        // head: p in [0, p0), both rows
        if (lane < p0) {
            unsigned t = tab[lane];
            float u0 = *(const float*)(bu0 + (t & 0xFFFFu));
            float v0 = *(const float*)(bv0 + (t >> 16));
            float u1 = *(const float*)(bu1 + (t & 0xFFFFu));
            float v1 = *(const float*)(bv1 + (t >> 16));
            __stcs(po0 + lane, fmaxf(u0 + v0, 0.f));
            __stcs(po1 + lane, fmaxf(u1 + v1, 0.f));
        }

        // main: 22 warp-iterations, both rows per iteration (2 indep chains)
        float* q0 = po0 + p0;
        float* q1 = po1 + p0;
        #pragma unroll
        for (int it = 0; it < 22; it++) {
            unsigned t = tw[it];
            unsigned ui = t & 0xFFFFu, vi = t >> 16;
            float u0 = *(const float*)(bu0 + ui);
            float v0 = *(const float*)(bv0 + vi);
            float u1 = *(const float*)(bu1 + ui);
            float v1 = *(const float*)(bv1 + vi);
            __stcs(q0 + it * 32 + lane, fmaxf(u0 + v0, 0.f));
            __stcs(q1 + it * 32 + lane, fmaxf(u1 + v1, 0.f));
        }

        // tail: p in [p0+704, 741), both rows
        int p = p0 + 704 + lane;
        #pragma unroll
        for (int tt = 0; tt < 2; tt++) {
            if (p < PN) {
                unsigned t = tab[p];
                float u0 = *(const float*)(bu0 + (t & 0xFFFFu));
                float v0 = *(const float*)(bv0 + (t >> 16));
                float u1 = *(const float*)(bu1 + (t & 0xFFFFu));
                float v1 = *(const float*)(bv1 + (t >> 16));
                __stcs(po0 + p, fmaxf(u0 + v0, 0.f));
                __stcs(po1 + p, fmaxf(u1 + v1, 0.f));
            }
            p += 32;
        }
    }
}

extern "C" void kernel_launch(void* const* d_in, const int* in_sizes, int n_in,
                              void* d_out, int out_size)
{
    const float* x    = (const float*)d_in[0];
    const float* W    = (const float*)d_in[1];
    const float* bias = (const float*)d_in[2];
    float* out = (float*)d_out;

    const int B = in_sizes[0] / (FN * EN);   // 2048

    cudaFuncSetAttribute(interconv_kernel,
                         cudaFuncAttributeMaxDynamicSharedMemorySize, SMEM_BYTES);
    interconv_kernel<<<B, THREADS, SMEM_BYTES>>>(x, W, bias, out);
}